// round 13
// baseline (speedup 1.0000x reference)
#include <cuda_runtime.h>
#include <cuda_fp16.h>
#include <math.h>

// ---------------- problem constants ----------------
#define NN   50000
#define EEX  450000
#define GG   64
#define DMAX 544
#define EPS_BN 1e-5f
#define NEG_SLOPE 0.2f

// ---------------- static scratch ----------------
__device__ float  d_hx [(size_t)NN * DMAX];   // L2/3 scores etc.
__device__ __half d_hh [(size_t)NN * 320];    // L1 features fp16
__device__ float  d_sc [(size_t)NN * 40];     // L1 scores fp32
__device__ float  d_agg[(size_t)NN * 512];
__device__ float  d_lin[(size_t)NN * 64];
__device__ float  d_aggx[(size_t)NN * 256];
__device__ float  d_bcat[128 * DMAX];
__device__ int    d_deg[NN];
__device__ int    d_off[NN + 1];
__device__ int    d_cursor[NN];
__device__ int    d_csr[EEX];
__device__ int    d_partial[128];
__device__ float  d_bnsum[512];
__device__ float  d_bnsq [512];
__device__ float  d_scale[512];
__device__ float  d_shift[512];
__device__ float  d_pool[GG * 384];
__device__ int    d_cnt [GG];
__device__ float  d_pooled[GG * 384];

// ---------------- small utility kernels ----------------
__global__ void zero_i_kernel(int* p, int n) {
    int t = blockIdx.x * blockDim.x + threadIdx.x;
    if (t < n) p[t] = 0;
}
__global__ void zero_stats_kernel(float* s, float* q) {
    int t = threadIdx.x;
    if (t < 512) { s[t] = 0.f; q[t] = 0.f; }
}
__global__ void zero_pool_kernel(float* pool, int* cnt) {
    int t = blockIdx.x * blockDim.x + threadIdx.x;
    if (t < GG * 384) pool[t] = 0.f;
    if (t < GG) cnt[t] = 0;
}

// ---------------- CSR build ----------------
__global__ void edge_hist_kernel(const int* __restrict__ ei, int E, int n, int* deg) {
    int t = blockIdx.x * blockDim.x + threadIdx.x;
    int total = E + n;
    if (t >= total) return;
    int dst = (t < E) ? ei[E + t] : (t - E);
    atomicAdd(&deg[dst], 1);
}

__global__ void scan_block_kernel(const int* __restrict__ deg, int* off, int* partial, int n) {
    __shared__ int sm[1024];
    int gid = blockIdx.x * 1024 + threadIdx.x;
    int v = (gid < n) ? deg[gid] : 0;
    sm[threadIdx.x] = v;
    __syncthreads();
    for (int d = 1; d < 1024; d <<= 1) {
        int t = (threadIdx.x >= d) ? sm[threadIdx.x - d] : 0;
        __syncthreads();
        sm[threadIdx.x] += t;
        __syncthreads();
    }
    if (gid < n) off[gid] = sm[threadIdx.x] - v;
    if (threadIdx.x == 1023) partial[blockIdx.x] = sm[1023];
}

__global__ void scan_add_kernel(int* off, const int* __restrict__ partial, int* cursor,
                                int n, int total) {
    int gid = blockIdx.x * blockDim.x + threadIdx.x;
    if (gid < n) {
        int pb = gid >> 10;
        int base = 0;
        for (int j = 0; j < pb; j++) base += partial[j];
        int v = off[gid] + base;
        off[gid] = v;
        cursor[gid] = v;
    }
    if (gid == 0) off[n] = total;
}

__global__ void edge_scatter_kernel(const int* __restrict__ ei, int E, int n,
                                    int* cursor, int* csr_src) {
    int t = blockIdx.x * blockDim.x + threadIdx.x;
    int total = E + n;
    if (t >= total) return;
    int src, dst;
    if (t < E) { src = ei[t]; dst = ei[E + t]; }
    else       { src = t - E; dst = t - E; }
    int pos = atomicAdd(&cursor[dst], 1);
    csr_src[pos] = src;
}

// ---------------- weight preprocessing ----------------
__global__ void build_bcat_kernel(const float* __restrict__ W,
                                  const float* __restrict__ a_s,
                                  const float* __restrict__ a_d,
                                  float* __restrict__ bcat, int K, int H, int C) {
    int HC = H * C;
    int NC = HC + 2 * H;
    int idx = blockIdx.x * blockDim.x + threadIdx.x;
    if (idx >= K * NC) return;
    int k = idx / NC, col = idx % NC;
    if (col < HC) {
        bcat[idx] = W[(size_t)k * HC + col];
    } else {
        int hh = col - HC;
        const float* a = (hh >= H) ? a_d : a_s;
        if (hh >= H) hh -= H;
        float s = 0.f;
        for (int c = 0; c < C; c++) s += W[(size_t)k * HC + hh * C + c] * a[hh * C + c];
        bcat[idx] = s;
    }
}

__global__ void build_bsc_kernel(const float* __restrict__ W,
                                 const float* __restrict__ a_s,
                                 const float* __restrict__ a_d,
                                 float* __restrict__ bsc, int K, int H, int C) {
    int HC = H * C;
    int NC = 2 * H;
    int idx = blockIdx.x * blockDim.x + threadIdx.x;
    if (idx >= K * NC) return;
    int k = idx / NC, col = idx % NC;
    int hh = (col >= H) ? col - H : col;
    const float* a = (col >= H) ? a_d : a_s;
    float s = 0.f;
    for (int c = 0; c < C; c++) s += W[(size_t)k * HC + hh * C + c] * a[hh * C + c];
    bsc[idx] = s;
}

// ---------------- tensor-core GEMM (3xTF32, pre-split smem) ----------------
#define GBM 128
#define GBN 64
#define GBK 16

__device__ __forceinline__ void split_tf32(float x, unsigned& hi, unsigned& lo) {
    unsigned h_;
    asm("cvt.rna.tf32.f32 %0, %1;" : "=r"(h_) : "f"(x));
    float lf = x - __uint_as_float(h_);
    unsigned l_;
    asm("cvt.rna.tf32.f32 %0, %1;" : "=r"(l_) : "f"(lf));
    hi = h_; lo = l_;
}

__device__ __forceinline__ void mma_tf32(float c[4], const unsigned a[4], const unsigned b[2]) {
    asm volatile(
        "mma.sync.aligned.m16n8k8.row.col.f32.tf32.tf32.f32 "
        "{%0,%1,%2,%3}, {%4,%5,%6,%7}, {%8,%9}, {%0,%1,%2,%3};"
        : "+f"(c[0]), "+f"(c[1]), "+f"(c[2]), "+f"(c[3])
        : "r"(a[0]), "r"(a[1]), "r"(a[2]), "r"(a[3]), "r"(b[0]), "r"(b[1]));
}

__global__ __launch_bounds__(256) void gemm_tc_kernel(
    const float* __restrict__ A, const float* __restrict__ B,
    const float* __restrict__ bias,
    const float* __restrict__ tscale, const float* __restrict__ tshift,
    float* __restrict__ C_, __half* __restrict__ Hout, float* __restrict__ Sout,
    int hcols, float* ssum, float* ssq, int M, int K, int N)
{
    __shared__ unsigned AsH[GBK][GBM + 4];
    __shared__ unsigned AsL[GBK][GBM + 4];
    __shared__ unsigned BsH[GBK][GBN + 4];
    __shared__ unsigned BsL[GBK][GBN + 4];
    __shared__ float redS[GBN], redQ[GBN];
    int tid = threadIdx.x;
    int warp = tid >> 5, lane = tid & 31;
    int wm = warp & 3, wn = warp >> 2;
    int row0 = blockIdx.y * GBM;
    int col0 = blockIdx.x * GBN;
    int g = lane >> 2, t4 = lane & 3;

    float c[2][4][4];
    #pragma unroll
    for (int mm = 0; mm < 2; mm++)
        #pragma unroll
        for (int nn = 0; nn < 4; nn++)
            #pragma unroll
            for (int q = 0; q < 4; q++) c[mm][nn][q] = 0.f;

    for (int k0 = 0; k0 < K; k0 += GBK) {
        #pragma unroll
        for (int i = 0; i < 2; i++) {
            int idx = tid + 256 * i;
            int r = idx >> 2, c4 = idx & 3;
            int gr = row0 + r;
            float4 v = make_float4(0.f, 0.f, 0.f, 0.f);
            if (gr < M) v = *(const float4*)&A[(size_t)gr * K + k0 + c4 * 4];
            if (tscale) {
                int kb = k0 + c4 * 4;
                v.x = fmaxf(v.x * tscale[kb+0] + tshift[kb+0], 0.f);
                v.y = fmaxf(v.y * tscale[kb+1] + tshift[kb+1], 0.f);
                v.z = fmaxf(v.z * tscale[kb+2] + tshift[kb+2], 0.f);
                v.w = fmaxf(v.w * tscale[kb+3] + tshift[kb+3], 0.f);
            }
            unsigned hi, lo;
            split_tf32(v.x, hi, lo); AsH[c4*4+0][r] = hi; AsL[c4*4+0][r] = lo;
            split_tf32(v.y, hi, lo); AsH[c4*4+1][r] = hi; AsL[c4*4+1][r] = lo;
            split_tf32(v.z, hi, lo); AsH[c4*4+2][r] = hi; AsL[c4*4+2][r] = lo;
            split_tf32(v.w, hi, lo); AsH[c4*4+3][r] = hi; AsL[c4*4+3][r] = lo;
        }
        #pragma unroll
        for (int i = 0; i < 4; i++) {
            int idx = tid + 256 * i;
            int r = idx >> 6, cc = idx & 63;
            int gc = col0 + cc;
            float v = 0.f;
            if (gc < N) v = B[(size_t)(k0 + r) * N + gc];
            unsigned hi, lo;
            split_tf32(v, hi, lo);
            BsH[r][cc] = hi; BsL[r][cc] = lo;
        }
        __syncthreads();

        #pragma unroll
        for (int ks = 0; ks < GBK; ks += 8) {
            unsigned ahi[2][4], alo[2][4], bhi[4][2], blo[4][2];
            #pragma unroll
            for (int mm = 0; mm < 2; mm++) {
                int mrow = wm * 32 + mm * 16 + g;
                ahi[mm][0] = AsH[ks + t4][mrow];      alo[mm][0] = AsL[ks + t4][mrow];
                ahi[mm][1] = AsH[ks + t4][mrow + 8];  alo[mm][1] = AsL[ks + t4][mrow + 8];
                ahi[mm][2] = AsH[ks + t4 + 4][mrow];  alo[mm][2] = AsL[ks + t4 + 4][mrow];
                ahi[mm][3] = AsH[ks + t4 + 4][mrow+8];alo[mm][3] = AsL[ks + t4 + 4][mrow+8];
            }
            #pragma unroll
            for (int nn = 0; nn < 4; nn++) {
                int ncol = wn * 32 + nn * 8 + g;
                bhi[nn][0] = BsH[ks + t4][ncol];      blo[nn][0] = BsL[ks + t4][ncol];
                bhi[nn][1] = BsH[ks + t4 + 4][ncol];  blo[nn][1] = BsL[ks + t4 + 4][ncol];
            }
            #pragma unroll
            for (int mm = 0; mm < 2; mm++)
                #pragma unroll
                for (int nn = 0; nn < 4; nn++) {
                    mma_tf32(c[mm][nn], ahi[mm], bhi[nn]);
                    mma_tf32(c[mm][nn], alo[mm], bhi[nn]);
                    mma_tf32(c[mm][nn], ahi[mm], blo[nn]);
                }
        }
        __syncthreads();
    }

    // ---- epilogue: bias, then either split fp16/fp32 output or fp32 ----
    #pragma unroll
    for (int mm = 0; mm < 2; mm++) {
        int rbase = row0 + wm * 32 + mm * 16 + g;
        #pragma unroll
        for (int nn = 0; nn < 4; nn++) {
            int cbase = col0 + wn * 32 + nn * 8 + t4 * 2;
            #pragma unroll
            for (int rh = 0; rh < 2; rh++) {
                int rr = rbase + rh * 8;
                if (rr >= M) continue;
                float v0 = c[mm][nn][2*rh + 0];
                float v1 = c[mm][nn][2*rh + 1];
                int cc = cbase;
                if (bias && cc < N)     v0 += bias[cc];
                if (bias && cc + 1 < N) v1 += bias[cc + 1];
                c[mm][nn][2*rh + 0] = v0;
                c[mm][nn][2*rh + 1] = v1;
                if (Hout) {
                    if (cc + 1 < hcols) {
                        // paired half2 store (4B, coalesced within quad)
                        *(__half2*)&Hout[(size_t)rr * hcols + cc] =
                            __floats2half2_rn(v0, v1);
                    } else if (cc < N) {
                        int scN = N - hcols;
                        if (cc >= hcols) {
                            Sout[(size_t)rr * scN + (cc - hcols)] = v0;
                            if (cc + 1 < N) Sout[(size_t)rr * scN + (cc + 1 - hcols)] = v1;
                        }
                    }
                } else {
                    if (cc < N)     C_[(size_t)rr * N + cc]     = v0;
                    if (cc + 1 < N) C_[(size_t)rr * N + cc + 1] = v1;
                }
            }
        }
    }

    if (ssum) {
        if (tid < GBN) { redS[tid] = 0.f; redQ[tid] = 0.f; }
        __syncthreads();
        #pragma unroll
        for (int nn = 0; nn < 4; nn++) {
            #pragma unroll
            for (int par = 0; par < 2; par++) {
                int lcol = wn * 32 + nn * 8 + t4 * 2 + par;
                int cc = col0 + lcol;
                if (cc >= N) continue;
                float s = 0.f, q2 = 0.f;
                #pragma unroll
                for (int mm = 0; mm < 2; mm++) {
                    #pragma unroll
                    for (int rh = 0; rh < 2; rh++) {
                        int rr = row0 + wm * 32 + mm * 16 + g + rh * 8;
                        if (rr < M) {
                            float v = c[mm][nn][par + 2 * rh];
                            s += v; q2 += v * v;
                        }
                    }
                }
                atomicAdd(&redS[lcol], s);
                atomicAdd(&redQ[lcol], q2);
            }
        }
        __syncthreads();
        if (tid < GBN && col0 + tid < N) {
            atomicAdd(&ssum[col0 + tid], redS[tid]);
            atomicAdd(&ssq [col0 + tid], redQ[tid]);
        }
    }
}

// ---------------- L1 aggregation: fp16 features + fp32 scores + BN stats --
__global__ void gat_agg_l1_kernel(const __half2* __restrict__ hh,
                                  const float* __restrict__ sc,
                                  const int* __restrict__ off,
                                  const int* __restrict__ csr_src,
                                  const float* __restrict__ bias,
                                  float* __restrict__ out,
                                  float* ssum, float* ssq, int M) {
    constexpr int H = 20, C = 16, HC = 320;
    constexpr int N2 = HC / 64;   // 5 half2 per lane
    __shared__ float sS[HC], sQ[HC];
    int tid = threadIdx.x;
    for (int i = tid; i < HC; i += blockDim.x) { sS[i] = 0.f; sQ[i] = 0.f; }
    __syncthreads();

    int warp = (blockIdx.x * blockDim.x + tid) >> 5;
    int lane = tid & 31;
    bool valid = (warp < M);
    int i = valid ? warp : 0;
    int beg = off[i], end = off[i + 1];

    float sd = (lane < H) ? sc[(size_t)i * 40 + H + lane] : 0.f;
    float z = 0.f;
    float2 acc[N2];
    int hd[N2];
    #pragma unroll
    for (int j = 0; j < N2; j++) {
        acc[j] = make_float2(0.f, 0.f);
        hd[j] = (lane + 32 * j) / 8;   // head of half2 pair (C/2 = 8 pairs/head)
    }

    if (valid) {
        for (int p = beg; p < end; p++) {
            int s = __ldg(&csr_src[p]);
            float ev = 0.f;
            if (lane < H) {
                float v = __ldg(&sc[(size_t)s * 40 + lane]) + sd;
                v = (v > 0.f) ? v : NEG_SLOPE * v;
                ev = __expf(v);
                z += ev;
            }
            const __half2* hrow = hh + (size_t)s * (HC / 2);
            #pragma unroll
            for (int j = 0; j < N2; j++) {
                float a = __shfl_sync(0xffffffffu, ev, hd[j]);
                float2 hv = __half22float2(__ldg(&hrow[lane + 32 * j]));
                acc[j].x += a * hv.x;
                acc[j].y += a * hv.y;
            }
        }
        float zinv = (lane < H) ? 1.f / (z + 1e-16f) : 0.f;
        const float2* b2 = (const float2*)bias;
        float2* o2 = (float2*)(out + (size_t)i * HC);
        #pragma unroll
        for (int j = 0; j < N2; j++) {
            float zi = __shfl_sync(0xffffffffu, zinv, hd[j]);
            int idx = lane + 32 * j;
            float2 bb = b2[idx];
            float ox = acc[j].x * zi + bb.x;
            float oy = acc[j].y * zi + bb.y;
            o2[idx] = make_float2(ox, oy);
            atomicAdd(&sS[2*idx],   ox);
            atomicAdd(&sS[2*idx+1], oy);
            atomicAdd(&sQ[2*idx],   ox*ox);
            atomicAdd(&sQ[2*idx+1], oy*oy);
        }
    }
    __syncthreads();
    for (int f = tid; f < HC; f += blockDim.x) {
        atomicAdd(&ssum[f], sS[f]);
        atomicAdd(&ssq [f], sQ[f]);
    }
}

// ---------------- L2/L3 input-side aggregation ---------------------------
template <int H, int DIN>
__global__ void gat_aggx_kernel(const float* __restrict__ xin,
                                const float* __restrict__ sc,
                                const float* __restrict__ bnscale,
                                const float* __restrict__ bnshift,
                                const int* __restrict__ off,
                                const int* __restrict__ csr_src,
                                float* __restrict__ aggx, int M) {
    constexpr int NACC = (H * DIN) / 32;
    int warp = (blockIdx.x * blockDim.x + threadIdx.x) >> 5;
    int lane = threadIdx.x & 31;
    if (warp >= M) return;
    int i = warp;
    int beg = off[i], end = off[i + 1];

    int k = lane & (DIN - 1);
    float bsc = bnscale[k], bsh = bnshift[k];
    float sd = (lane < H) ? sc[(size_t)i * 2 * H + H + lane] : 0.f;

    float z = 0.f;
    float acc[NACC];
    int hd[NACC];
    #pragma unroll
    for (int j = 0; j < NACC; j++) {
        acc[j] = 0.f;
        hd[j] = (lane + 32 * j) / DIN;
    }

    for (int p = beg; p < end; p++) {
        int s = __ldg(&csr_src[p]);
        float ev = 0.f;
        if (lane < H) {
            float v = __ldg(&sc[(size_t)s * 2 * H + lane]) + sd;
            v = (v > 0.f) ? v : NEG_SLOPE * v;
            ev = __expf(v);
            z += ev;
        }
        float xv = fmaxf(__ldg(&xin[(size_t)s * DIN + k]) * bsc + bsh, 0.f);
        #pragma unroll
        for (int j = 0; j < NACC; j++) {
            float a = __shfl_sync(0xffffffffu, ev, hd[j]);
            acc[j] += a * xv;
        }
    }
    float zinv = (lane < H) ? 1.f / (z + 1e-16f) : 0.f;
    float* orow = aggx + (size_t)i * (H * DIN);
    #pragma unroll
    for (int j = 0; j < NACC; j++) {
        float zi = __shfl_sync(0xffffffffu, zinv, hd[j]);
        orow[lane + 32 * j] = acc[j] * zi;
    }
}

// ---------------- per-head linear + fused BN stats ----------------------
template <int H, int DIN, int C, int NB>
__global__ void headlin_kernel(const float* __restrict__ aggx,
                               const float* __restrict__ W,
                               const float* __restrict__ bias,
                               float* __restrict__ out,
                               float* ssum, float* ssq, int M) {
    constexpr int HC = H * C;
    constexpr int HD = H * DIN;
    extern __shared__ float smem[];
    float* Wsm = smem;
    float* ax  = smem + DIN * HC;
    int tid = threadIdx.x;             // HC threads
    int h = tid / C;

    for (int i = tid; i < DIN * HC; i += HC) Wsm[i] = W[i];

    int n0 = blockIdx.x * NB;
    for (int i = tid; i < NB * HD; i += HC) {
        int r = i / HD, cc = i % HD;
        int n = n0 + r;
        ax[i] = (n < M) ? aggx[(size_t)n * HD + cc] : 0.f;
    }
    __syncthreads();

    float bb = bias[tid];
    float s = 0.f, q2 = 0.f;
    #pragma unroll
    for (int r = 0; r < NB; r++) {
        int n = n0 + r;
        if (n >= M) break;
        float acc = 0.f;
        const float* axr = ax + r * HD + h * DIN;
        #pragma unroll
        for (int k = 0; k < DIN; k++)
            acc += Wsm[k * HC + tid] * axr[k];
        float v = acc + bb;
        out[(size_t)n * HC + tid] = v;
        s += v; q2 += v * v;
    }
    atomicAdd(&ssum[tid], s);
    atomicAdd(&ssq [tid], q2);
}

// ---------------- BN finalize (reads + zeroes accumulators) --------------
__global__ void bn_finalize_kernel(float* ssum, float* ssq,
                                   const float* __restrict__ g, const float* __restrict__ be,
                                   float* scale, float* shift, int M, int D) {
    int f = blockIdx.x * blockDim.x + threadIdx.x;
    if (f >= D) return;
    float inv = 1.f / (float)M;
    float mu = ssum[f] * inv;
    float var = ssq[f] * inv - mu * mu;
    float sc = g[f] * rsqrtf(var + EPS_BN);
    scale[f] = sc;
    shift[f] = be[f] - mu * sc;
    ssum[f] = 0.f;
    ssq [f] = 0.f;
}

// ---------------- pooling: segmented + BN3+ReLU ----------
#define POOL_ROWS 128
__global__ void pool_bn_kernel(const float* __restrict__ h, const int* __restrict__ batch,
                               const float* __restrict__ scale, const float* __restrict__ shift,
                               float* pool, int* cnt, int M) {
    const int D = 384;
    int f = threadIdx.x;
    int r0 = blockIdx.x * POOL_ROWS;
    int rend = min(r0 + POOL_ROWS, M);
    float sc = scale[f], sh = shift[f];
    int cur = __ldg(&batch[r0]);
    float acc = 0.f;
    int count = 0;
    for (int r = r0; r < rend; r++) {
        int b = __ldg(&batch[r]);
        if (b != cur) {
            atomicAdd(&pool[cur * D + f], acc);
            if (f == 0) atomicAdd(&cnt[cur], count);
            acc = 0.f; count = 0; cur = b;
        }
        acc += fmaxf(h[(size_t)r * D + f] * sc + sh, 0.f);
        count++;
    }
    atomicAdd(&pool[cur * D + f], acc);
    if (f == 0) atomicAdd(&cnt[cur], count);
}

__global__ void pool_div_kernel(float* pooled, const float* pool, const int* cnt, int G, int D) {
    int t = blockIdx.x * blockDim.x + threadIdx.x;
    if (t >= G * D) return;
    int g = t / D;
    float c = fmaxf((float)cnt[g], 1.f);
    pooled[t] = pool[t] / c;
}

// ---------------- host-side orchestration ----------------
struct Ptrs {
    float *hx, *agg, *lin, *aggx, *bcat, *sc;
    __half *hh;
    int *deg, *off, *cursor, *csr, *partial;
    float *bnsum, *bnsq, *scale, *shift, *pool, *pooled;
    int *cnt;
};

static void launch_gemm(const float* A, const float* B, const float* bias,
                        const float* tscale, const float* tshift, float* C,
                        __half* Hout, float* Sout, int hcols,
                        float* ssum, float* ssq, int M, int K, int N) {
    dim3 grid((N + GBN - 1) / GBN, (M + GBM - 1) / GBM);
    gemm_tc_kernel<<<grid, 256>>>(A, B, bias, tscale, tshift, C,
                                  Hout, Sout, hcols, ssum, ssq, M, K, N);
}

extern "C" void kernel_launch(void* const* d_in, const int* in_sizes, int n_in,
                              void* d_out, int out_size) {
    const float* x     = (const float*)d_in[0];
    const int*   ei    = (const int*)  d_in[1];
    const int*   batch = (const int*)  d_in[2];
    const float* W1  = (const float*)d_in[3];
    const float* as1 = (const float*)d_in[4];
    const float* ad1 = (const float*)d_in[5];
    const float* b1  = (const float*)d_in[6];
    const float* g1  = (const float*)d_in[7];
    const float* be1 = (const float*)d_in[8];
    const float* lw1 = (const float*)d_in[9];
    const float* lb1 = (const float*)d_in[10];
    const float* gl1 = (const float*)d_in[11];
    const float* bel1= (const float*)d_in[12];
    const float* W2  = (const float*)d_in[13];
    const float* as2 = (const float*)d_in[14];
    const float* ad2 = (const float*)d_in[15];
    const float* b2  = (const float*)d_in[16];
    const float* g2  = (const float*)d_in[17];
    const float* be2 = (const float*)d_in[18];
    const float* lw2 = (const float*)d_in[19];
    const float* lb2 = (const float*)d_in[20];
    const float* gl2 = (const float*)d_in[21];
    const float* bel2= (const float*)d_in[22];
    const float* W3  = (const float*)d_in[23];
    const float* as3 = (const float*)d_in[24];
    const float* ad3 = (const float*)d_in[25];
    const float* b3  = (const float*)d_in[26];
    const float* g3  = (const float*)d_in[27];
    const float* be3 = (const float*)d_in[28];
    const float* lwf = (const float*)d_in[29];
    const float* lbf = (const float*)d_in[30];

    int M = in_sizes[2];
    int E = in_sizes[1] / 2;
    int EX = E + M;

    Ptrs P;
    cudaGetSymbolAddress((void**)&P.hx, d_hx);
    cudaGetSymbolAddress((void**)&P.hh, d_hh);
    cudaGetSymbolAddress((void**)&P.sc, d_sc);
    cudaGetSymbolAddress((void**)&P.agg, d_agg);
    cudaGetSymbolAddress((void**)&P.lin, d_lin);
    cudaGetSymbolAddress((void**)&P.aggx, d_aggx);
    cudaGetSymbolAddress((void**)&P.bcat, d_bcat);
    cudaGetSymbolAddress((void**)&P.deg, d_deg);
    cudaGetSymbolAddress((void**)&P.off, d_off);
    cudaGetSymbolAddress((void**)&P.cursor, d_cursor);
    cudaGetSymbolAddress((void**)&P.csr, d_csr);
    cudaGetSymbolAddress((void**)&P.partial, d_partial);
    cudaGetSymbolAddress((void**)&P.bnsum, d_bnsum);
    cudaGetSymbolAddress((void**)&P.bnsq, d_bnsq);
    cudaGetSymbolAddress((void**)&P.scale, d_scale);
    cudaGetSymbolAddress((void**)&P.shift, d_shift);
    cudaGetSymbolAddress((void**)&P.pool, d_pool);
    cudaGetSymbolAddress((void**)&P.pooled, d_pooled);
    cudaGetSymbolAddress((void**)&P.cnt, d_cnt);

    cudaFuncSetAttribute(headlin_kernel<8, 32, 48, 4>,
                         cudaFuncAttributeMaxDynamicSharedMemorySize, 56 * 1024);
    cudaFuncSetAttribute(headlin_kernel<16, 16, 32, 4>,
                         cudaFuncAttributeMaxDynamicSharedMemorySize, 56 * 1024);

    // ---- init + CSR build ----
    zero_stats_kernel<<<1, 512>>>(P.bnsum, P.bnsq);
    zero_i_kernel<<<(M + 255) / 256, 256>>>(P.deg, M);
    edge_hist_kernel<<<(EX + 255) / 256, 256>>>(ei, E, M, P.deg);
    int nb = (M + 1023) / 1024;
    scan_block_kernel<<<nb, 1024>>>(P.deg, P.off, P.partial, M);
    scan_add_kernel<<<(M + 255) / 256, 256>>>(P.off, P.partial, P.cursor, M, EX);
    edge_scatter_kernel<<<(EX + 255) / 256, 256>>>(ei, E, M, P.cursor, P.csr);

    const int wpb = 8;
    int ablk = (M + wpb - 1) / wpb;

    // ---- Layer 1: GAT(128 -> 20x16=320), NC=360, fp16 features ----
    build_bcat_kernel<<<(128 * 360 + 255) / 256, 256>>>(W1, as1, ad1, P.bcat, 128, 20, 16);
    launch_gemm(x, P.bcat, nullptr, nullptr, nullptr, nullptr, P.hh, P.sc, 320,
                nullptr, nullptr, M, 128, 360);
    gat_agg_l1_kernel<<<ablk, wpb * 32>>>((const __half2*)P.hh, P.sc, P.off, P.csr,
                                          b1, P.agg, P.bnsum, P.bnsq, M);
    bn_finalize_kernel<<<3, 128>>>(P.bnsum, P.bnsq, g1, be1, P.scale, P.shift, M, 320);
    launch_gemm(P.agg, lw1, lb1, P.scale, P.shift, P.lin, nullptr, nullptr, 0,
                P.bnsum, P.bnsq, M, 320, 16);
    bn_finalize_kernel<<<1, 128>>>(P.bnsum, P.bnsq, gl1, bel1, P.scale, P.shift, M, 16);

    // ---- Layer 2: GAT(16 -> 16x32=512) via input-side aggregation ----
    build_bsc_kernel<<<(16 * 32 + 255) / 256, 256>>>(W2, as2, ad2, P.bcat, 16, 16, 32);
    launch_gemm(P.lin, P.bcat, nullptr, P.scale, P.shift, P.hx, nullptr, nullptr, 0,
                nullptr, nullptr, M, 16, 32);
    gat_aggx_kernel<16, 16><<<ablk, wpb * 32>>>(P.lin, P.hx, P.scale, P.shift, P.off, P.csr, P.aggx, M);
    {
        int smem = (16 * 512 + 4 * 256) * 4;
        headlin_kernel<16, 16, 32, 4><<<(M + 3) / 4, 512, smem>>>(P.aggx, W2, b2, P.agg, P.bnsum, P.bnsq, M);
    }
    bn_finalize_kernel<<<4, 128>>>(P.bnsum, P.bnsq, g2, be2, P.scale, P.shift, M, 512);
    launch_gemm(P.agg, lw2, lb2, P.scale, P.shift, P.lin, nullptr, nullptr, 0,
                P.bnsum, P.bnsq, M, 512, 32);
    bn_finalize_kernel<<<1, 128>>>(P.bnsum, P.bnsq, gl2, bel2, P.scale, P.shift, M, 32);

    // ---- Layer 3: GAT(32 -> 8x48=384) via input-side aggregation ----
    build_bsc_kernel<<<(32 * 16 + 255) / 256, 256>>>(W3, as3, ad3, P.bcat, 32, 8, 48);
    launch_gemm(P.lin, P.bcat, nullptr, P.scale, P.shift, P.hx, nullptr, nullptr, 0,
                nullptr, nullptr, M, 32, 16);
    gat_aggx_kernel<8, 32><<<ablk, wpb * 32>>>(P.lin, P.hx, P.scale, P.shift, P.off, P.csr, P.aggx, M);
    {
        int smem = (32 * 384 + 4 * 256) * 4;
        headlin_kernel<8, 32, 48, 4><<<(M + 3) / 4, 384, smem>>>(P.aggx, W3, b3, P.agg, P.bnsum, P.bnsq, M);
    }
    bn_finalize_kernel<<<3, 128>>>(P.bnsum, P.bnsq, g3, be3, P.scale, P.shift, M, 384);

    // ---- global mean pool (fused BN3+ReLU, segmented) + final linear ----
    zero_pool_kernel<<<(GG * 384 + 255) / 256, 256>>>(P.pool, P.cnt);
    pool_bn_kernel<<<(M + POOL_ROWS - 1) / POOL_ROWS, 384>>>(P.agg, batch, P.scale, P.shift, P.pool, P.cnt, M);
    pool_div_kernel<<<(GG * 384 + 255) / 256, 256>>>(P.pooled, P.pool, P.cnt, GG, 384);
    launch_gemm(P.pooled, lwf, lbf, nullptr, nullptr, (float*)d_out, nullptr, nullptr, 0,
                nullptr, nullptr, GG, 384, 10);
}

// round 14
// speedup vs baseline: 1.1220x; 1.1220x over previous
#include <cuda_runtime.h>
#include <cuda_fp16.h>
#include <math.h>

// ---------------- problem constants ----------------
#define NN   50000
#define EEX  450000
#define GG   64
#define DMAX 544
#define EPS_BN 1e-5f
#define NEG_SLOPE 0.2f

// ---------------- static scratch ----------------
__device__ float  d_hx [(size_t)NN * DMAX];   // L1: [h|s_src|s_dst]; L2/3: scores
__device__ float  d_agg[(size_t)NN * 512];
__device__ float  d_lin[(size_t)NN * 64];
__device__ float  d_aggx[(size_t)NN * 256];
__device__ float  d_bcat[128 * DMAX];
__device__ int    d_deg[NN];
__device__ int    d_off[NN + 1];
__device__ int    d_cursor[NN];
__device__ int    d_csr[EEX];
__device__ int    d_partial[128];
__device__ float  d_bnsum[512];
__device__ float  d_bnsq [512];
__device__ float  d_scale[512];
__device__ float  d_shift[512];
__device__ float  d_pool[GG * 384];
__device__ int    d_cnt [GG];
__device__ float  d_pooled[GG * 384];

// ---------------- small utility kernels ----------------
__global__ void zero_i_kernel(int* p, int n) {
    int t = blockIdx.x * blockDim.x + threadIdx.x;
    if (t < n) p[t] = 0;
}
__global__ void zero_stats_kernel(float* s, float* q) {
    int t = threadIdx.x;
    if (t < 512) { s[t] = 0.f; q[t] = 0.f; }
}
__global__ void zero_pool_kernel(float* pool, int* cnt) {
    int t = blockIdx.x * blockDim.x + threadIdx.x;
    if (t < GG * 384) pool[t] = 0.f;
    if (t < GG) cnt[t] = 0;
}

// ---------------- CSR build ----------------
__global__ void edge_hist_kernel(const int* __restrict__ ei, int E, int n, int* deg) {
    int t = blockIdx.x * blockDim.x + threadIdx.x;
    int total = E + n;
    if (t >= total) return;
    int dst = (t < E) ? ei[E + t] : (t - E);
    atomicAdd(&deg[dst], 1);
}

__global__ void scan_block_kernel(const int* __restrict__ deg, int* off, int* partial, int n) {
    __shared__ int sm[1024];
    int gid = blockIdx.x * 1024 + threadIdx.x;
    int v = (gid < n) ? deg[gid] : 0;
    sm[threadIdx.x] = v;
    __syncthreads();
    for (int d = 1; d < 1024; d <<= 1) {
        int t = (threadIdx.x >= d) ? sm[threadIdx.x - d] : 0;
        __syncthreads();
        sm[threadIdx.x] += t;
        __syncthreads();
    }
    if (gid < n) off[gid] = sm[threadIdx.x] - v;
    if (threadIdx.x == 1023) partial[blockIdx.x] = sm[1023];
}

__global__ void scan_add_kernel(int* off, const int* __restrict__ partial, int* cursor,
                                int n, int total) {
    int gid = blockIdx.x * blockDim.x + threadIdx.x;
    if (gid < n) {
        int pb = gid >> 10;
        int base = 0;
        for (int j = 0; j < pb; j++) base += partial[j];
        int v = off[gid] + base;
        off[gid] = v;
        cursor[gid] = v;
    }
    if (gid == 0) off[n] = total;
}

__global__ void edge_scatter_kernel(const int* __restrict__ ei, int E, int n,
                                    int* cursor, int* csr_src) {
    int t = blockIdx.x * blockDim.x + threadIdx.x;
    int total = E + n;
    if (t >= total) return;
    int src, dst;
    if (t < E) { src = ei[t]; dst = ei[E + t]; }
    else       { src = t - E; dst = t - E; }
    int pos = atomicAdd(&cursor[dst], 1);
    csr_src[pos] = src;
}

// ---------------- weight preprocessing ----------------
__global__ void build_bcat_kernel(const float* __restrict__ W,
                                  const float* __restrict__ a_s,
                                  const float* __restrict__ a_d,
                                  float* __restrict__ bcat, int K, int H, int C) {
    int HC = H * C;
    int NC = HC + 2 * H;
    int idx = blockIdx.x * blockDim.x + threadIdx.x;
    if (idx >= K * NC) return;
    int k = idx / NC, col = idx % NC;
    if (col < HC) {
        bcat[idx] = W[(size_t)k * HC + col];
    } else {
        int hh = col - HC;
        const float* a = (hh >= H) ? a_d : a_s;
        if (hh >= H) hh -= H;
        float s = 0.f;
        for (int c = 0; c < C; c++) s += W[(size_t)k * HC + hh * C + c] * a[hh * C + c];
        bcat[idx] = s;
    }
}

__global__ void build_bsc_kernel(const float* __restrict__ W,
                                 const float* __restrict__ a_s,
                                 const float* __restrict__ a_d,
                                 float* __restrict__ bsc, int K, int H, int C) {
    int HC = H * C;
    int NC = 2 * H;
    int idx = blockIdx.x * blockDim.x + threadIdx.x;
    if (idx >= K * NC) return;
    int k = idx / NC, col = idx % NC;
    int hh = (col >= H) ? col - H : col;
    const float* a = (col >= H) ? a_d : a_s;
    float s = 0.f;
    for (int c = 0; c < C; c++) s += W[(size_t)k * HC + hh * C + c] * a[hh * C + c];
    bsc[idx] = s;
}

// ---------------- tensor-core GEMM (3xTF32, pre-split smem) ----------------
#define GBM 128
#define GBN 64
#define GBK 16

__device__ __forceinline__ void split_tf32(float x, unsigned& hi, unsigned& lo) {
    unsigned h_;
    asm("cvt.rna.tf32.f32 %0, %1;" : "=r"(h_) : "f"(x));
    float lf = x - __uint_as_float(h_);
    unsigned l_;
    asm("cvt.rna.tf32.f32 %0, %1;" : "=r"(l_) : "f"(lf));
    hi = h_; lo = l_;
}

__device__ __forceinline__ void mma_tf32(float c[4], const unsigned a[4], const unsigned b[2]) {
    asm volatile(
        "mma.sync.aligned.m16n8k8.row.col.f32.tf32.tf32.f32 "
        "{%0,%1,%2,%3}, {%4,%5,%6,%7}, {%8,%9}, {%0,%1,%2,%3};"
        : "+f"(c[0]), "+f"(c[1]), "+f"(c[2]), "+f"(c[3])
        : "r"(a[0]), "r"(a[1]), "r"(a[2]), "r"(a[3]), "r"(b[0]), "r"(b[1]));
}

__global__ __launch_bounds__(256) void gemm_tc_kernel(
    const float* __restrict__ A, const float* __restrict__ B,
    const float* __restrict__ bias,
    const float* __restrict__ tscale, const float* __restrict__ tshift,
    float* __restrict__ C_, float* ssum, float* ssq, int M, int K, int N)
{
    __shared__ unsigned AsH[GBK][GBM + 4];
    __shared__ unsigned AsL[GBK][GBM + 4];
    __shared__ unsigned BsH[GBK][GBN + 4];
    __shared__ unsigned BsL[GBK][GBN + 4];
    __shared__ float redS[GBN], redQ[GBN];
    int tid = threadIdx.x;
    int warp = tid >> 5, lane = tid & 31;
    int wm = warp & 3, wn = warp >> 2;
    int row0 = blockIdx.y * GBM;
    int col0 = blockIdx.x * GBN;
    int g = lane >> 2, t4 = lane & 3;

    float c[2][4][4];
    #pragma unroll
    for (int mm = 0; mm < 2; mm++)
        #pragma unroll
        for (int nn = 0; nn < 4; nn++)
            #pragma unroll
            for (int q = 0; q < 4; q++) c[mm][nn][q] = 0.f;

    for (int k0 = 0; k0 < K; k0 += GBK) {
        #pragma unroll
        for (int i = 0; i < 2; i++) {
            int idx = tid + 256 * i;
            int r = idx >> 2, c4 = idx & 3;
            int gr = row0 + r;
            float4 v = make_float4(0.f, 0.f, 0.f, 0.f);
            if (gr < M) v = *(const float4*)&A[(size_t)gr * K + k0 + c4 * 4];
            if (tscale) {
                int kb = k0 + c4 * 4;
                v.x = fmaxf(v.x * tscale[kb+0] + tshift[kb+0], 0.f);
                v.y = fmaxf(v.y * tscale[kb+1] + tshift[kb+1], 0.f);
                v.z = fmaxf(v.z * tscale[kb+2] + tshift[kb+2], 0.f);
                v.w = fmaxf(v.w * tscale[kb+3] + tshift[kb+3], 0.f);
            }
            unsigned hi, lo;
            split_tf32(v.x, hi, lo); AsH[c4*4+0][r] = hi; AsL[c4*4+0][r] = lo;
            split_tf32(v.y, hi, lo); AsH[c4*4+1][r] = hi; AsL[c4*4+1][r] = lo;
            split_tf32(v.z, hi, lo); AsH[c4*4+2][r] = hi; AsL[c4*4+2][r] = lo;
            split_tf32(v.w, hi, lo); AsH[c4*4+3][r] = hi; AsL[c4*4+3][r] = lo;
        }
        #pragma unroll
        for (int i = 0; i < 4; i++) {
            int idx = tid + 256 * i;
            int r = idx >> 6, cc = idx & 63;
            int gc = col0 + cc;
            float v = 0.f;
            if (gc < N) v = B[(size_t)(k0 + r) * N + gc];
            unsigned hi, lo;
            split_tf32(v, hi, lo);
            BsH[r][cc] = hi; BsL[r][cc] = lo;
        }
        __syncthreads();

        #pragma unroll
        for (int ks = 0; ks < GBK; ks += 8) {
            unsigned ahi[2][4], alo[2][4], bhi[4][2], blo[4][2];
            #pragma unroll
            for (int mm = 0; mm < 2; mm++) {
                int mrow = wm * 32 + mm * 16 + g;
                ahi[mm][0] = AsH[ks + t4][mrow];      alo[mm][0] = AsL[ks + t4][mrow];
                ahi[mm][1] = AsH[ks + t4][mrow + 8];  alo[mm][1] = AsL[ks + t4][mrow + 8];
                ahi[mm][2] = AsH[ks + t4 + 4][mrow];  alo[mm][2] = AsL[ks + t4 + 4][mrow];
                ahi[mm][3] = AsH[ks + t4 + 4][mrow+8];alo[mm][3] = AsL[ks + t4 + 4][mrow+8];
            }
            #pragma unroll
            for (int nn = 0; nn < 4; nn++) {
                int ncol = wn * 32 + nn * 8 + g;
                bhi[nn][0] = BsH[ks + t4][ncol];      blo[nn][0] = BsL[ks + t4][ncol];
                bhi[nn][1] = BsH[ks + t4 + 4][ncol];  blo[nn][1] = BsL[ks + t4 + 4][ncol];
            }
            #pragma unroll
            for (int mm = 0; mm < 2; mm++)
                #pragma unroll
                for (int nn = 0; nn < 4; nn++) {
                    mma_tf32(c[mm][nn], ahi[mm], bhi[nn]);
                    mma_tf32(c[mm][nn], alo[mm], bhi[nn]);
                    mma_tf32(c[mm][nn], ahi[mm], blo[nn]);
                }
        }
        __syncthreads();
    }

    // add bias into accumulators, then store
    #pragma unroll
    for (int mm = 0; mm < 2; mm++) {
        int rbase = row0 + wm * 32 + mm * 16 + g;
        #pragma unroll
        for (int nn = 0; nn < 4; nn++) {
            int cbase = col0 + wn * 32 + nn * 8 + t4 * 2;
            #pragma unroll
            for (int q = 0; q < 4; q++) {
                int rr = rbase + ((q >= 2) ? 8 : 0);
                int cc = cbase + (q & 1);
                if (rr < M && cc < N) {
                    float v = c[mm][nn][q];
                    if (bias) v += bias[cc];
                    c[mm][nn][q] = v;
                    C_[(size_t)rr * N + cc] = v;
                }
            }
        }
    }

    // fused BN stats over output columns
    if (ssum) {
        if (tid < GBN) { redS[tid] = 0.f; redQ[tid] = 0.f; }
        __syncthreads();
        #pragma unroll
        for (int nn = 0; nn < 4; nn++) {
            #pragma unroll
            for (int par = 0; par < 2; par++) {
                int lcol = wn * 32 + nn * 8 + t4 * 2 + par;
                int cc = col0 + lcol;
                if (cc >= N) continue;
                float s = 0.f, q2 = 0.f;
                #pragma unroll
                for (int mm = 0; mm < 2; mm++) {
                    #pragma unroll
                    for (int rh = 0; rh < 2; rh++) {
                        int rr = row0 + wm * 32 + mm * 16 + g + rh * 8;
                        if (rr < M) {
                            float v = c[mm][nn][par + 2 * rh];
                            s += v; q2 += v * v;
                        }
                    }
                }
                atomicAdd(&redS[lcol], s);
                atomicAdd(&redQ[lcol], q2);
            }
        }
        __syncthreads();
        if (tid < GBN && col0 + tid < N) {
            atomicAdd(&ssum[col0 + tid], redS[tid]);
            atomicAdd(&ssq [col0 + tid], redQ[tid]);
        }
    }
}

// ---------------- L1 fused single-pass GAT aggregation + BN stats --------
// Edge loop unrolled x2 for memory-level parallelism.
template <int H, int C>
__global__ void gat_aggregate_kernel(const float* __restrict__ hx,
                                     const int* __restrict__ off,
                                     const int* __restrict__ csr_src,
                                     const float* __restrict__ bias,
                                     float* __restrict__ out,
                                     float* ssum, float* ssq, int M) {
    constexpr int HC = H * C;
    constexpr int NSTR = HC + 2 * H;
    constexpr int N2 = HC / 64;
    __shared__ float sS[HC], sQ[HC];
    int tid = threadIdx.x;
    for (int i = tid; i < HC; i += blockDim.x) { sS[i] = 0.f; sQ[i] = 0.f; }
    __syncthreads();

    int warp = (blockIdx.x * blockDim.x + tid) >> 5;
    int lane = tid & 31;
    bool valid = (warp < M);
    int i = valid ? warp : 0;
    int beg = off[i], end = off[i + 1];

    float sd = (lane < H) ? hx[(size_t)i * NSTR + HC + H + lane] : 0.f;
    float z = 0.f;
    float2 acc[N2];
    int hd[N2];
    #pragma unroll
    for (int j = 0; j < N2; j++) {
        acc[j] = make_float2(0.f, 0.f);
        hd[j] = (2 * (lane + 32 * j)) / C;
    }

    if (valid) {
        int p = beg;
        for (; p + 1 < end; p += 2) {
            int s0 = __ldg(&csr_src[p]);
            int s1 = __ldg(&csr_src[p + 1]);
            const float* row0 = hx + (size_t)s0 * NSTR;
            const float* row1 = hx + (size_t)s1 * NSTR;
            float ev0 = 0.f, ev1 = 0.f;
            if (lane < H) {
                float v0 = __ldg(&row0[HC + lane]) + sd;
                float v1 = __ldg(&row1[HC + lane]) + sd;
                v0 = (v0 > 0.f) ? v0 : NEG_SLOPE * v0;
                v1 = (v1 > 0.f) ? v1 : NEG_SLOPE * v1;
                ev0 = __expf(v0);
                ev1 = __expf(v1);
                z += ev0 + ev1;
            }
            const float2* h0 = (const float2*)row0;
            const float2* h1 = (const float2*)row1;
            #pragma unroll
            for (int j = 0; j < N2; j++) {
                float a0 = __shfl_sync(0xffffffffu, ev0, hd[j]);
                float a1 = __shfl_sync(0xffffffffu, ev1, hd[j]);
                float2 x0 = __ldg(&h0[lane + 32 * j]);
                float2 x1 = __ldg(&h1[lane + 32 * j]);
                acc[j].x += a0 * x0.x + a1 * x1.x;
                acc[j].y += a0 * x0.y + a1 * x1.y;
            }
        }
        if (p < end) {
            int s = __ldg(&csr_src[p]);
            const float* row = hx + (size_t)s * NSTR;
            float ev = 0.f;
            if (lane < H) {
                float v = __ldg(&row[HC + lane]) + sd;
                v = (v > 0.f) ? v : NEG_SLOPE * v;
                ev = __expf(v);
                z += ev;
            }
            const float2* hrow = (const float2*)row;
            #pragma unroll
            for (int j = 0; j < N2; j++) {
                float a = __shfl_sync(0xffffffffu, ev, hd[j]);
                float2 hv = __ldg(&hrow[lane + 32 * j]);
                acc[j].x += a * hv.x;
                acc[j].y += a * hv.y;
            }
        }
        float zinv = (lane < H) ? 1.f / (z + 1e-16f) : 0.f;
        const float2* b2 = (const float2*)bias;
        float2* o2 = (float2*)(out + (size_t)i * HC);
        #pragma unroll
        for (int j = 0; j < N2; j++) {
            float zi = __shfl_sync(0xffffffffu, zinv, hd[j]);
            int idx = lane + 32 * j;
            float2 bb = b2[idx];
            float ox = acc[j].x * zi + bb.x;
            float oy = acc[j].y * zi + bb.y;
            o2[idx] = make_float2(ox, oy);
            atomicAdd(&sS[2*idx],   ox);
            atomicAdd(&sS[2*idx+1], oy);
            atomicAdd(&sQ[2*idx],   ox*ox);
            atomicAdd(&sQ[2*idx+1], oy*oy);
        }
    }
    __syncthreads();
    for (int f = tid; f < HC; f += blockDim.x) {
        atomicAdd(&ssum[f], sS[f]);
        atomicAdd(&ssq [f], sQ[f]);
    }
}

// ---------------- L2/L3 input-side aggregation (unrolled x2) -------------
template <int H, int DIN>
__global__ void gat_aggx_kernel(const float* __restrict__ xin,
                                const float* __restrict__ sc,
                                const float* __restrict__ bnscale,
                                const float* __restrict__ bnshift,
                                const int* __restrict__ off,
                                const int* __restrict__ csr_src,
                                float* __restrict__ aggx, int M) {
    constexpr int NACC = (H * DIN) / 32;
    int warp = (blockIdx.x * blockDim.x + threadIdx.x) >> 5;
    int lane = threadIdx.x & 31;
    if (warp >= M) return;
    int i = warp;
    int beg = off[i], end = off[i + 1];

    int k = lane & (DIN - 1);
    float bsc = bnscale[k], bsh = bnshift[k];
    float sd = (lane < H) ? sc[(size_t)i * 2 * H + H + lane] : 0.f;

    float z = 0.f;
    float acc[NACC];
    int hd[NACC];
    #pragma unroll
    for (int j = 0; j < NACC; j++) {
        acc[j] = 0.f;
        hd[j] = (lane + 32 * j) / DIN;
    }

    int p = beg;
    for (; p + 1 < end; p += 2) {
        int s0 = __ldg(&csr_src[p]);
        int s1 = __ldg(&csr_src[p + 1]);
        float ev0 = 0.f, ev1 = 0.f;
        if (lane < H) {
            float v0 = __ldg(&sc[(size_t)s0 * 2 * H + lane]) + sd;
            float v1 = __ldg(&sc[(size_t)s1 * 2 * H + lane]) + sd;
            v0 = (v0 > 0.f) ? v0 : NEG_SLOPE * v0;
            v1 = (v1 > 0.f) ? v1 : NEG_SLOPE * v1;
            ev0 = __expf(v0);
            ev1 = __expf(v1);
            z += ev0 + ev1;
        }
        float x0 = fmaxf(__ldg(&xin[(size_t)s0 * DIN + k]) * bsc + bsh, 0.f);
        float x1 = fmaxf(__ldg(&xin[(size_t)s1 * DIN + k]) * bsc + bsh, 0.f);
        #pragma unroll
        for (int j = 0; j < NACC; j++) {
            float a0 = __shfl_sync(0xffffffffu, ev0, hd[j]);
            float a1 = __shfl_sync(0xffffffffu, ev1, hd[j]);
            acc[j] += a0 * x0 + a1 * x1;
        }
    }
    if (p < end) {
        int s = __ldg(&csr_src[p]);
        float ev = 0.f;
        if (lane < H) {
            float v = __ldg(&sc[(size_t)s * 2 * H + lane]) + sd;
            v = (v > 0.f) ? v : NEG_SLOPE * v;
            ev = __expf(v);
            z += ev;
        }
        float xv = fmaxf(__ldg(&xin[(size_t)s * DIN + k]) * bsc + bsh, 0.f);
        #pragma unroll
        for (int j = 0; j < NACC; j++) {
            float a = __shfl_sync(0xffffffffu, ev, hd[j]);
            acc[j] += a * xv;
        }
    }
    float zinv = (lane < H) ? 1.f / (z + 1e-16f) : 0.f;
    float* orow = aggx + (size_t)i * (H * DIN);
    #pragma unroll
    for (int j = 0; j < NACC; j++) {
        float zi = __shfl_sync(0xffffffffu, zinv, hd[j]);
        orow[lane + 32 * j] = acc[j] * zi;
    }
}

// ---------------- per-head linear + fused BN stats ----------------------
template <int H, int DIN, int C, int NB>
__global__ void headlin_kernel(const float* __restrict__ aggx,
                               const float* __restrict__ W,
                               const float* __restrict__ bias,
                               float* __restrict__ out,
                               float* ssum, float* ssq, int M) {
    constexpr int HC = H * C;
    constexpr int HD = H * DIN;
    extern __shared__ float smem[];
    float* Wsm = smem;
    float* ax  = smem + DIN * HC;
    int tid = threadIdx.x;             // HC threads
    int h = tid / C;

    for (int i = tid; i < DIN * HC; i += HC) Wsm[i] = W[i];

    int n0 = blockIdx.x * NB;
    for (int i = tid; i < NB * HD; i += HC) {
        int r = i / HD, cc = i % HD;
        int n = n0 + r;
        ax[i] = (n < M) ? aggx[(size_t)n * HD + cc] : 0.f;
    }
    __syncthreads();

    float bb = bias[tid];
    float s = 0.f, q2 = 0.f;
    #pragma unroll
    for (int r = 0; r < NB; r++) {
        int n = n0 + r;
        if (n >= M) break;
        float acc = 0.f;
        const float* axr = ax + r * HD + h * DIN;
        #pragma unroll
        for (int k = 0; k < DIN; k++)
            acc += Wsm[k * HC + tid] * axr[k];
        float v = acc + bb;
        out[(size_t)n * HC + tid] = v;
        s += v; q2 += v * v;
    }
    atomicAdd(&ssum[tid], s);
    atomicAdd(&ssq [tid], q2);
}

// ---------------- BN finalize (reads + zeroes accumulators) --------------
__global__ void bn_finalize_kernel(float* ssum, float* ssq,
                                   const float* __restrict__ g, const float* __restrict__ be,
                                   float* scale, float* shift, int M, int D) {
    int f = blockIdx.x * blockDim.x + threadIdx.x;
    if (f >= D) return;
    float inv = 1.f / (float)M;
    float mu = ssum[f] * inv;
    float var = ssq[f] * inv - mu * mu;
    float sc = g[f] * rsqrtf(var + EPS_BN);
    scale[f] = sc;
    shift[f] = be[f] - mu * sc;
    ssum[f] = 0.f;
    ssq [f] = 0.f;
}

// ---------------- pooling: segmented + BN3+ReLU ----------
#define POOL_ROWS 128
__global__ void pool_bn_kernel(const float* __restrict__ h, const int* __restrict__ batch,
                               const float* __restrict__ scale, const float* __restrict__ shift,
                               float* pool, int* cnt, int M) {
    const int D = 384;
    int f = threadIdx.x;
    int r0 = blockIdx.x * POOL_ROWS;
    int rend = min(r0 + POOL_ROWS, M);
    float sc = scale[f], sh = shift[f];
    int cur = __ldg(&batch[r0]);
    float acc = 0.f;
    int count = 0;
    for (int r = r0; r < rend; r++) {
        int b = __ldg(&batch[r]);
        if (b != cur) {
            atomicAdd(&pool[cur * D + f], acc);
            if (f == 0) atomicAdd(&cnt[cur], count);
            acc = 0.f; count = 0; cur = b;
        }
        acc += fmaxf(h[(size_t)r * D + f] * sc + sh, 0.f);
        count++;
    }
    atomicAdd(&pool[cur * D + f], acc);
    if (f == 0) atomicAdd(&cnt[cur], count);
}

__global__ void pool_div_kernel(float* pooled, const float* pool, const int* cnt, int G, int D) {
    int t = blockIdx.x * blockDim.x + threadIdx.x;
    if (t >= G * D) return;
    int g = t / D;
    float c = fmaxf((float)cnt[g], 1.f);
    pooled[t] = pool[t] / c;
}

// ---------------- host-side orchestration ----------------
struct Ptrs {
    float *hx, *agg, *lin, *aggx, *bcat;
    int *deg, *off, *cursor, *csr, *partial;
    float *bnsum, *bnsq, *scale, *shift, *pool, *pooled;
    int *cnt;
};

static void launch_gemm(const float* A, const float* B, const float* bias,
                        const float* tscale, const float* tshift, float* C,
                        float* ssum, float* ssq, int M, int K, int N) {
    dim3 grid((N + GBN - 1) / GBN, (M + GBM - 1) / GBM);
    gemm_tc_kernel<<<grid, 256>>>(A, B, bias, tscale, tshift, C, ssum, ssq, M, K, N);
}

extern "C" void kernel_launch(void* const* d_in, const int* in_sizes, int n_in,
                              void* d_out, int out_size) {
    const float* x     = (const float*)d_in[0];
    const int*   ei    = (const int*)  d_in[1];
    const int*   batch = (const int*)  d_in[2];
    const float* W1  = (const float*)d_in[3];
    const float* as1 = (const float*)d_in[4];
    const float* ad1 = (const float*)d_in[5];
    const float* b1  = (const float*)d_in[6];
    const float* g1  = (const float*)d_in[7];
    const float* be1 = (const float*)d_in[8];
    const float* lw1 = (const float*)d_in[9];
    const float* lb1 = (const float*)d_in[10];
    const float* gl1 = (const float*)d_in[11];
    const float* bel1= (const float*)d_in[12];
    const float* W2  = (const float*)d_in[13];
    const float* as2 = (const float*)d_in[14];
    const float* ad2 = (const float*)d_in[15];
    const float* b2  = (const float*)d_in[16];
    const float* g2  = (const float*)d_in[17];
    const float* be2 = (const float*)d_in[18];
    const float* lw2 = (const float*)d_in[19];
    const float* lb2 = (const float*)d_in[20];
    const float* gl2 = (const float*)d_in[21];
    const float* bel2= (const float*)d_in[22];
    const float* W3  = (const float*)d_in[23];
    const float* as3 = (const float*)d_in[24];
    const float* ad3 = (const float*)d_in[25];
    const float* b3  = (const float*)d_in[26];
    const float* g3  = (const float*)d_in[27];
    const float* be3 = (const float*)d_in[28];
    const float* lwf = (const float*)d_in[29];
    const float* lbf = (const float*)d_in[30];

    int M = in_sizes[2];
    int E = in_sizes[1] / 2;
    int EX = E + M;

    Ptrs P;
    cudaGetSymbolAddress((void**)&P.hx, d_hx);
    cudaGetSymbolAddress((void**)&P.agg, d_agg);
    cudaGetSymbolAddress((void**)&P.lin, d_lin);
    cudaGetSymbolAddress((void**)&P.aggx, d_aggx);
    cudaGetSymbolAddress((void**)&P.bcat, d_bcat);
    cudaGetSymbolAddress((void**)&P.deg, d_deg);
    cudaGetSymbolAddress((void**)&P.off, d_off);
    cudaGetSymbolAddress((void**)&P.cursor, d_cursor);
    cudaGetSymbolAddress((void**)&P.csr, d_csr);
    cudaGetSymbolAddress((void**)&P.partial, d_partial);
    cudaGetSymbolAddress((void**)&P.bnsum, d_bnsum);
    cudaGetSymbolAddress((void**)&P.bnsq, d_bnsq);
    cudaGetSymbolAddress((void**)&P.scale, d_scale);
    cudaGetSymbolAddress((void**)&P.shift, d_shift);
    cudaGetSymbolAddress((void**)&P.pool, d_pool);
    cudaGetSymbolAddress((void**)&P.pooled, d_pooled);
    cudaGetSymbolAddress((void**)&P.cnt, d_cnt);

    cudaFuncSetAttribute(headlin_kernel<8, 32, 48, 4>,
                         cudaFuncAttributeMaxDynamicSharedMemorySize, 56 * 1024);
    cudaFuncSetAttribute(headlin_kernel<16, 16, 32, 4>,
                         cudaFuncAttributeMaxDynamicSharedMemorySize, 56 * 1024);

    // ---- init + CSR build ----
    zero_stats_kernel<<<1, 512>>>(P.bnsum, P.bnsq);
    zero_i_kernel<<<(M + 255) / 256, 256>>>(P.deg, M);
    edge_hist_kernel<<<(EX + 255) / 256, 256>>>(ei, E, M, P.deg);
    int nb = (M + 1023) / 1024;
    scan_block_kernel<<<nb, 1024>>>(P.deg, P.off, P.partial, M);
    scan_add_kernel<<<(M + 255) / 256, 256>>>(P.off, P.partial, P.cursor, M, EX);
    edge_scatter_kernel<<<(EX + 255) / 256, 256>>>(ei, E, M, P.cursor, P.csr);

    const int wpb = 8;
    int ablk = (M + wpb - 1) / wpb;

    // ---- Layer 1: GAT(128 -> 20x16=320), NC=360 ----
    build_bcat_kernel<<<(128 * 360 + 255) / 256, 256>>>(W1, as1, ad1, P.bcat, 128, 20, 16);
    launch_gemm(x, P.bcat, nullptr, nullptr, nullptr, P.hx, nullptr, nullptr, M, 128, 360);
    gat_aggregate_kernel<20, 16><<<ablk, wpb * 32>>>(P.hx, P.off, P.csr, b1, P.agg, P.bnsum, P.bnsq, M);
    bn_finalize_kernel<<<3, 128>>>(P.bnsum, P.bnsq, g1, be1, P.scale, P.shift, M, 320);
    launch_gemm(P.agg, lw1, lb1, P.scale, P.shift, P.lin, P.bnsum, P.bnsq, M, 320, 16);
    bn_finalize_kernel<<<1, 128>>>(P.bnsum, P.bnsq, gl1, bel1, P.scale, P.shift, M, 16);

    // ---- Layer 2: GAT(16 -> 16x32=512) via input-side aggregation ----
    build_bsc_kernel<<<(16 * 32 + 255) / 256, 256>>>(W2, as2, ad2, P.bcat, 16, 16, 32);
    launch_gemm(P.lin, P.bcat, nullptr, P.scale, P.shift, P.hx, nullptr, nullptr, M, 16, 32);
    gat_aggx_kernel<16, 16><<<ablk, wpb * 32>>>(P.lin, P.hx, P.scale, P.shift, P.off, P.csr, P.aggx, M);
    {
        int smem = (16 * 512 + 4 * 256) * 4;
        headlin_kernel<16, 16, 32, 4><<<(M + 3) / 4, 512, smem>>>(P.aggx, W2, b2, P.agg, P.bnsum, P.bnsq, M);
    }
    bn_finalize_kernel<<<4, 128>>>(P.bnsum, P.bnsq, g2, be2, P.scale, P.shift, M, 512);
    launch_gemm(P.agg, lw2, lb2, P.scale, P.shift, P.lin, P.bnsum, P.bnsq, M, 512, 32);
    bn_finalize_kernel<<<1, 128>>>(P.bnsum, P.bnsq, gl2, bel2, P.scale, P.shift, M, 32);

    // ---- Layer 3: GAT(32 -> 8x48=384) via input-side aggregation ----
    build_bsc_kernel<<<(32 * 16 + 255) / 256, 256>>>(W3, as3, ad3, P.bcat, 32, 8, 48);
    launch_gemm(P.lin, P.bcat, nullptr, P.scale, P.shift, P.hx, nullptr, nullptr, M, 32, 16);
    gat_aggx_kernel<8, 32><<<ablk, wpb * 32>>>(P.lin, P.hx, P.scale, P.shift, P.off, P.csr, P.aggx, M);
    {
        int smem = (32 * 384 + 4 * 256) * 4;
        headlin_kernel<8, 32, 48, 4><<<(M + 3) / 4, 384, smem>>>(P.aggx, W3, b3, P.agg, P.bnsum, P.bnsq, M);
    }
    bn_finalize_kernel<<<3, 128>>>(P.bnsum, P.bnsq, g3, be3, P.scale, P.shift, M, 384);

    // ---- global mean pool (fused BN3+ReLU, segmented) + final linear ----
    zero_pool_kernel<<<(GG * 384 + 255) / 256, 256>>>(P.pool, P.cnt);
    pool_bn_kernel<<<(M + POOL_ROWS - 1) / POOL_ROWS, 384>>>(P.agg, batch, P.scale, P.shift, P.pool, P.cnt, M);
    pool_div_kernel<<<(GG * 384 + 255) / 256, 256>>>(P.pooled, P.pool, P.cnt, GG, 384);
    launch_gemm(P.pooled, lwf, lbf, nullptr, nullptr, (float*)d_out, nullptr, nullptr, GG, 384, 10);
}

// round 17
// speedup vs baseline: 1.1957x; 1.0658x over previous
#include <cuda_runtime.h>
#include <cuda_fp16.h>
#include <math.h>

// ---------------- problem constants ----------------
#define NN   50000
#define EEX  450000
#define GG   64
#define DMAX 544
#define EPS_BN 1e-5f
#define NEG_SLOPE 0.2f

// ---------------- static scratch ----------------
__device__ float  d_hx [(size_t)NN * DMAX];   // L1: [h|s_src|s_dst]; L2/3: scores
__device__ float  d_agg[(size_t)NN * 512];
__device__ float  d_lin[(size_t)NN * 64];
__device__ float  d_aggx[(size_t)NN * 256];
__device__ float  d_bcat[128 * DMAX];
__device__ int    d_deg[NN];
__device__ int    d_off[NN + 1];
__device__ int    d_cursor[NN];
__device__ int    d_csr[EEX];
__device__ int    d_partial[128];
__device__ float  d_bnsum[512];
__device__ float  d_bnsq [512];
__device__ float  d_scale[512];
__device__ float  d_shift[512];
__device__ float  d_pool[GG * 384];
__device__ int    d_cnt [GG];
__device__ float  d_pooled[GG * 384];

// ---------------- small utility kernels ----------------
__global__ void zero_i_kernel(int* p, int n) {
    int t = blockIdx.x * blockDim.x + threadIdx.x;
    if (t < n) p[t] = 0;
}
__global__ void zero_stats_kernel(float* s, float* q) {
    int t = threadIdx.x;
    if (t < 512) { s[t] = 0.f; q[t] = 0.f; }
}
__global__ void zero_pool_kernel(float* pool, int* cnt) {
    int t = blockIdx.x * blockDim.x + threadIdx.x;
    if (t < GG * 384) pool[t] = 0.f;
    if (t < GG) cnt[t] = 0;
}

// ---------------- CSR build ----------------
__global__ void edge_hist_kernel(const int* __restrict__ ei, int E, int n, int* deg) {
    int t = blockIdx.x * blockDim.x + threadIdx.x;
    int total = E + n;
    if (t >= total) return;
    int dst = (t < E) ? ei[E + t] : (t - E);
    atomicAdd(&deg[dst], 1);
}

__global__ void scan_block_kernel(const int* __restrict__ deg, int* off, int* partial, int n) {
    __shared__ int sm[1024];
    int gid = blockIdx.x * 1024 + threadIdx.x;
    int v = (gid < n) ? deg[gid] : 0;
    sm[threadIdx.x] = v;
    __syncthreads();
    for (int d = 1; d < 1024; d <<= 1) {
        int t = (threadIdx.x >= d) ? sm[threadIdx.x - d] : 0;
        __syncthreads();
        sm[threadIdx.x] += t;
        __syncthreads();
    }
    if (gid < n) off[gid] = sm[threadIdx.x] - v;
    if (threadIdx.x == 1023) partial[blockIdx.x] = sm[1023];
}

__global__ void scan_add_kernel(int* off, const int* __restrict__ partial, int* cursor,
                                int n, int total) {
    int gid = blockIdx.x * blockDim.x + threadIdx.x;
    if (gid < n) {
        int pb = gid >> 10;
        int base = 0;
        for (int j = 0; j < pb; j++) base += partial[j];
        int v = off[gid] + base;
        off[gid] = v;
        cursor[gid] = v;
    }
    if (gid == 0) off[n] = total;
}

__global__ void edge_scatter_kernel(const int* __restrict__ ei, int E, int n,
                                    int* cursor, int* csr_src) {
    int t = blockIdx.x * blockDim.x + threadIdx.x;
    int total = E + n;
    if (t >= total) return;
    int src, dst;
    if (t < E) { src = ei[t]; dst = ei[E + t]; }
    else       { src = t - E; dst = t - E; }
    int pos = atomicAdd(&cursor[dst], 1);
    csr_src[pos] = src;
}

// ---------------- weight preprocessing ----------------
__global__ void build_bcat_kernel(const float* __restrict__ W,
                                  const float* __restrict__ a_s,
                                  const float* __restrict__ a_d,
                                  float* __restrict__ bcat, int K, int H, int C) {
    int HC = H * C;
    int NC = HC + 2 * H;
    int idx = blockIdx.x * blockDim.x + threadIdx.x;
    if (idx >= K * NC) return;
    int k = idx / NC, col = idx % NC;
    if (col < HC) {
        bcat[idx] = W[(size_t)k * HC + col];
    } else {
        int hh = col - HC;
        const float* a = (hh >= H) ? a_d : a_s;
        if (hh >= H) hh -= H;
        float s = 0.f;
        for (int c = 0; c < C; c++) s += W[(size_t)k * HC + hh * C + c] * a[hh * C + c];
        bcat[idx] = s;
    }
}

__global__ void build_bsc_kernel(const float* __restrict__ W,
                                 const float* __restrict__ a_s,
                                 const float* __restrict__ a_d,
                                 float* __restrict__ bsc, int K, int H, int C) {
    int HC = H * C;
    int NC = 2 * H;
    int idx = blockIdx.x * blockDim.x + threadIdx.x;
    if (idx >= K * NC) return;
    int k = idx / NC, col = idx % NC;
    int hh = (col >= H) ? col - H : col;
    const float* a = (col >= H) ? a_d : a_s;
    float s = 0.f;
    for (int c = 0; c < C; c++) s += W[(size_t)k * HC + hh * C + c] * a[hh * C + c];
    bsc[idx] = s;
}

// ---------------- tensor-core GEMM (2x/3x TF32, pre-split smem) ------------
#define GBM 128
#define GBN 64
#define GBK 16

__device__ __forceinline__ void split_tf32(float x, unsigned& hi, unsigned& lo) {
    unsigned h_;
    asm("cvt.rna.tf32.f32 %0, %1;" : "=r"(h_) : "f"(x));
    float lf = x - __uint_as_float(h_);
    unsigned l_;
    asm("cvt.rna.tf32.f32 %0, %1;" : "=r"(l_) : "f"(lf));
    hi = h_; lo = l_;
}

__device__ __forceinline__ void mma_tf32(float c[4], const unsigned a[4], const unsigned b[2]) {
    asm volatile(
        "mma.sync.aligned.m16n8k8.row.col.f32.tf32.tf32.f32 "
        "{%0,%1,%2,%3}, {%4,%5,%6,%7}, {%8,%9}, {%0,%1,%2,%3};"
        : "+f"(c[0]), "+f"(c[1]), "+f"(c[2]), "+f"(c[3])
        : "r"(a[0]), "r"(a[1]), "r"(a[2]), "r"(a[3]), "r"(b[0]), "r"(b[1]));
}

// FULLB=1 -> 3xTF32 (adds ahi*blo term); FULLB=0 -> 2xTF32 (A exact, B hi only)
template <int FULLB>
__global__ __launch_bounds__(256) void gemm_tc_kernel(
    const float* __restrict__ A, const float* __restrict__ B,
    const float* __restrict__ bias,
    const float* __restrict__ tscale, const float* __restrict__ tshift,
    float* __restrict__ C_, float* ssum, float* ssq, int M, int K, int N)
{
    __shared__ unsigned AsH[GBK][GBM + 4];
    __shared__ unsigned AsL[GBK][GBM + 4];
    __shared__ unsigned BsH[GBK][GBN + 4];
    __shared__ unsigned BsL[GBK][GBN + 4];
    __shared__ float redS[GBN], redQ[GBN];
    int tid = threadIdx.x;
    int warp = tid >> 5, lane = tid & 31;
    int wm = warp & 3, wn = warp >> 2;
    int row0 = blockIdx.y * GBM;
    int col0 = blockIdx.x * GBN;
    int g = lane >> 2, t4 = lane & 3;

    float c[2][4][4];
    #pragma unroll
    for (int mm = 0; mm < 2; mm++)
        #pragma unroll
        for (int nn = 0; nn < 4; nn++)
            #pragma unroll
            for (int q = 0; q < 4; q++) c[mm][nn][q] = 0.f;

    for (int k0 = 0; k0 < K; k0 += GBK) {
        #pragma unroll
        for (int i = 0; i < 2; i++) {
            int idx = tid + 256 * i;
            int r = idx >> 2, c4 = idx & 3;
            int gr = row0 + r;
            float4 v = make_float4(0.f, 0.f, 0.f, 0.f);
            if (gr < M) v = *(const float4*)&A[(size_t)gr * K + k0 + c4 * 4];
            if (tscale) {
                int kb = k0 + c4 * 4;
                v.x = fmaxf(v.x * tscale[kb+0] + tshift[kb+0], 0.f);
                v.y = fmaxf(v.y * tscale[kb+1] + tshift[kb+1], 0.f);
                v.z = fmaxf(v.z * tscale[kb+2] + tshift[kb+2], 0.f);
                v.w = fmaxf(v.w * tscale[kb+3] + tshift[kb+3], 0.f);
            }
            unsigned hi, lo;
            split_tf32(v.x, hi, lo); AsH[c4*4+0][r] = hi; AsL[c4*4+0][r] = lo;
            split_tf32(v.y, hi, lo); AsH[c4*4+1][r] = hi; AsL[c4*4+1][r] = lo;
            split_tf32(v.z, hi, lo); AsH[c4*4+2][r] = hi; AsL[c4*4+2][r] = lo;
            split_tf32(v.w, hi, lo); AsH[c4*4+3][r] = hi; AsL[c4*4+3][r] = lo;
        }
        #pragma unroll
        for (int i = 0; i < 4; i++) {
            int idx = tid + 256 * i;
            int r = idx >> 6, cc = idx & 63;
            int gc = col0 + cc;
            float v = 0.f;
            if (gc < N) v = B[(size_t)(k0 + r) * N + gc];
            unsigned hi, lo;
            split_tf32(v, hi, lo);
            BsH[r][cc] = hi;
            if (FULLB) BsL[r][cc] = lo;
        }
        __syncthreads();

        #pragma unroll
        for (int ks = 0; ks < GBK; ks += 8) {
            unsigned ahi[2][4], alo[2][4], bhi[4][2], blo[4][2];
            #pragma unroll
            for (int mm = 0; mm < 2; mm++) {
                int mrow = wm * 32 + mm * 16 + g;
                ahi[mm][0] = AsH[ks + t4][mrow];      alo[mm][0] = AsL[ks + t4][mrow];
                ahi[mm][1] = AsH[ks + t4][mrow + 8];  alo[mm][1] = AsL[ks + t4][mrow + 8];
                ahi[mm][2] = AsH[ks + t4 + 4][mrow];  alo[mm][2] = AsL[ks + t4 + 4][mrow];
                ahi[mm][3] = AsH[ks + t4 + 4][mrow+8];alo[mm][3] = AsL[ks + t4 + 4][mrow+8];
            }
            #pragma unroll
            for (int nn = 0; nn < 4; nn++) {
                int ncol = wn * 32 + nn * 8 + g;
                bhi[nn][0] = BsH[ks + t4][ncol];
                bhi[nn][1] = BsH[ks + t4 + 4][ncol];
                if (FULLB) {
                    blo[nn][0] = BsL[ks + t4][ncol];
                    blo[nn][1] = BsL[ks + t4 + 4][ncol];
                }
            }
            #pragma unroll
            for (int mm = 0; mm < 2; mm++)
                #pragma unroll
                for (int nn = 0; nn < 4; nn++) {
                    mma_tf32(c[mm][nn], ahi[mm], bhi[nn]);
                    mma_tf32(c[mm][nn], alo[mm], bhi[nn]);
                    if (FULLB) mma_tf32(c[mm][nn], ahi[mm], blo[nn]);
                }
        }
        __syncthreads();
    }

    // add bias into accumulators, then store
    #pragma unroll
    for (int mm = 0; mm < 2; mm++) {
        int rbase = row0 + wm * 32 + mm * 16 + g;
        #pragma unroll
        for (int nn = 0; nn < 4; nn++) {
            int cbase = col0 + wn * 32 + nn * 8 + t4 * 2;
            #pragma unroll
            for (int q = 0; q < 4; q++) {
                int rr = rbase + ((q >= 2) ? 8 : 0);
                int cc = cbase + (q & 1);
                if (rr < M && cc < N) {
                    float v = c[mm][nn][q];
                    if (bias) v += bias[cc];
                    c[mm][nn][q] = v;
                    C_[(size_t)rr * N + cc] = v;
                }
            }
        }
    }

    // fused BN stats over output columns
    if (ssum) {
        if (tid < GBN) { redS[tid] = 0.f; redQ[tid] = 0.f; }
        __syncthreads();
        #pragma unroll
        for (int nn = 0; nn < 4; nn++) {
            #pragma unroll
            for (int par = 0; par < 2; par++) {
                int lcol = wn * 32 + nn * 8 + t4 * 2 + par;
                int cc = col0 + lcol;
                if (cc >= N) continue;
                float s = 0.f, q2 = 0.f;
                #pragma unroll
                for (int mm = 0; mm < 2; mm++) {
                    #pragma unroll
                    for (int rh = 0; rh < 2; rh++) {
                        int rr = row0 + wm * 32 + mm * 16 + g + rh * 8;
                        if (rr < M) {
                            float v = c[mm][nn][par + 2 * rh];
                            s += v; q2 += v * v;
                        }
                    }
                }
                atomicAdd(&redS[lcol], s);
                atomicAdd(&redQ[lcol], q2);
            }
        }
        __syncthreads();
        if (tid < GBN && col0 + tid < N) {
            atomicAdd(&ssum[col0 + tid], redS[tid]);
            atomicAdd(&ssq [col0 + tid], redQ[tid]);
        }
    }
}

// ---------------- L1 fused single-pass GAT aggregation + BN stats --------
template <int H, int C>
__global__ void gat_aggregate_kernel(const float* __restrict__ hx,
                                     const int* __restrict__ off,
                                     const int* __restrict__ csr_src,
                                     const float* __restrict__ bias,
                                     float* __restrict__ out,
                                     float* ssum, float* ssq, int M) {
    constexpr int HC = H * C;
    constexpr int NSTR = HC + 2 * H;
    constexpr int N2 = HC / 64;
    __shared__ float sS[HC], sQ[HC];
    int tid = threadIdx.x;
    for (int i = tid; i < HC; i += blockDim.x) { sS[i] = 0.f; sQ[i] = 0.f; }
    __syncthreads();

    int warp = (blockIdx.x * blockDim.x + tid) >> 5;
    int lane = tid & 31;
    bool valid = (warp < M);
    int i = valid ? warp : 0;
    int beg = off[i], end = off[i + 1];

    float sd = (lane < H) ? hx[(size_t)i * NSTR + HC + H + lane] : 0.f;
    float z = 0.f;
    float2 acc[N2];
    int hd[N2];
    #pragma unroll
    for (int j = 0; j < N2; j++) {
        acc[j] = make_float2(0.f, 0.f);
        hd[j] = (2 * (lane + 32 * j)) / C;
    }

    if (valid) {
        int p = beg;
        for (; p + 1 < end; p += 2) {
            int s0 = __ldg(&csr_src[p]);
            int s1 = __ldg(&csr_src[p + 1]);
            const float* row0 = hx + (size_t)s0 * NSTR;
            const float* row1 = hx + (size_t)s1 * NSTR;
            float ev0 = 0.f, ev1 = 0.f;
            if (lane < H) {
                float v0 = __ldg(&row0[HC + lane]) + sd;
                float v1 = __ldg(&row1[HC + lane]) + sd;
                v0 = (v0 > 0.f) ? v0 : NEG_SLOPE * v0;
                v1 = (v1 > 0.f) ? v1 : NEG_SLOPE * v1;
                ev0 = __expf(v0);
                ev1 = __expf(v1);
                z += ev0 + ev1;
            }
            const float2* h0 = (const float2*)row0;
            const float2* h1 = (const float2*)row1;
            #pragma unroll
            for (int j = 0; j < N2; j++) {
                float a0 = __shfl_sync(0xffffffffu, ev0, hd[j]);
                float a1 = __shfl_sync(0xffffffffu, ev1, hd[j]);
                float2 x0 = __ldg(&h0[lane + 32 * j]);
                float2 x1 = __ldg(&h1[lane + 32 * j]);
                acc[j].x += a0 * x0.x + a1 * x1.x;
                acc[j].y += a0 * x0.y + a1 * x1.y;
            }
        }
        if (p < end) {
            int s = __ldg(&csr_src[p]);
            const float* row = hx + (size_t)s * NSTR;
            float ev = 0.f;
            if (lane < H) {
                float v = __ldg(&row[HC + lane]) + sd;
                v = (v > 0.f) ? v : NEG_SLOPE * v;
                ev = __expf(v);
                z += ev;
            }
            const float2* hrow = (const float2*)row;
            #pragma unroll
            for (int j = 0; j < N2; j++) {
                float a = __shfl_sync(0xffffffffu, ev, hd[j]);
                float2 hv = __ldg(&hrow[lane + 32 * j]);
                acc[j].x += a * hv.x;
                acc[j].y += a * hv.y;
            }
        }
        float zinv = (lane < H) ? 1.f / (z + 1e-16f) : 0.f;
        const float2* b2 = (const float2*)bias;
        float2* o2 = (float2*)(out + (size_t)i * HC);
        #pragma unroll
        for (int j = 0; j < N2; j++) {
            float zi = __shfl_sync(0xffffffffu, zinv, hd[j]);
            int idx = lane + 32 * j;
            float2 bb = b2[idx];
            float ox = acc[j].x * zi + bb.x;
            float oy = acc[j].y * zi + bb.y;
            o2[idx] = make_float2(ox, oy);
            atomicAdd(&sS[2*idx],   ox);
            atomicAdd(&sS[2*idx+1], oy);
            atomicAdd(&sQ[2*idx],   ox*ox);
            atomicAdd(&sQ[2*idx+1], oy*oy);
        }
    }
    __syncthreads();
    for (int f = tid; f < HC; f += blockDim.x) {
        atomicAdd(&ssum[f], sS[f]);
        atomicAdd(&ssq [f], sQ[f]);
    }
}

// ---------------- L2/L3 input-side aggregation (unrolled x2) -------------
template <int H, int DIN>
__global__ void gat_aggx_kernel(const float* __restrict__ xin,
                                const float* __restrict__ sc,
                                const float* __restrict__ bnscale,
                                const float* __restrict__ bnshift,
                                const int* __restrict__ off,
                                const int* __restrict__ csr_src,
                                float* __restrict__ aggx, int M) {
    constexpr int NACC = (H * DIN) / 32;
    int warp = (blockIdx.x * blockDim.x + threadIdx.x) >> 5;
    int lane = threadIdx.x & 31;
    if (warp >= M) return;
    int i = warp;
    int beg = off[i], end = off[i + 1];

    int k = lane & (DIN - 1);
    float bsc = bnscale[k], bsh = bnshift[k];
    float sd = (lane < H) ? sc[(size_t)i * 2 * H + H + lane] : 0.f;

    float z = 0.f;
    float acc[NACC];
    int hd[NACC];
    #pragma unroll
    for (int j = 0; j < NACC; j++) {
        acc[j] = 0.f;
        hd[j] = (lane + 32 * j) / DIN;
    }

    int p = beg;
    for (; p + 1 < end; p += 2) {
        int s0 = __ldg(&csr_src[p]);
        int s1 = __ldg(&csr_src[p + 1]);
        float ev0 = 0.f, ev1 = 0.f;
        if (lane < H) {
            float v0 = __ldg(&sc[(size_t)s0 * 2 * H + lane]) + sd;
            float v1 = __ldg(&sc[(size_t)s1 * 2 * H + lane]) + sd;
            v0 = (v0 > 0.f) ? v0 : NEG_SLOPE * v0;
            v1 = (v1 > 0.f) ? v1 : NEG_SLOPE * v1;
            ev0 = __expf(v0);
            ev1 = __expf(v1);
            z += ev0 + ev1;
        }
        float x0 = fmaxf(__ldg(&xin[(size_t)s0 * DIN + k]) * bsc + bsh, 0.f);
        float x1 = fmaxf(__ldg(&xin[(size_t)s1 * DIN + k]) * bsc + bsh, 0.f);
        #pragma unroll
        for (int j = 0; j < NACC; j++) {
            float a0 = __shfl_sync(0xffffffffu, ev0, hd[j]);
            float a1 = __shfl_sync(0xffffffffu, ev1, hd[j]);
            acc[j] += a0 * x0 + a1 * x1;
        }
    }
    if (p < end) {
        int s = __ldg(&csr_src[p]);
        float ev = 0.f;
        if (lane < H) {
            float v = __ldg(&sc[(size_t)s * 2 * H + lane]) + sd;
            v = (v > 0.f) ? v : NEG_SLOPE * v;
            ev = __expf(v);
            z += ev;
        }
        float xv = fmaxf(__ldg(&xin[(size_t)s * DIN + k]) * bsc + bsh, 0.f);
        #pragma unroll
        for (int j = 0; j < NACC; j++) {
            float a = __shfl_sync(0xffffffffu, ev, hd[j]);
            acc[j] += a * xv;
        }
    }
    float zinv = (lane < H) ? 1.f / (z + 1e-16f) : 0.f;
    float* orow = aggx + (size_t)i * (H * DIN);
    #pragma unroll
    for (int j = 0; j < NACC; j++) {
        float zi = __shfl_sync(0xffffffffu, zinv, hd[j]);
        orow[lane + 32 * j] = acc[j] * zi;
    }
}

// ---------------- per-head linear + fused BN stats ----------------------
template <int H, int DIN, int C, int NB>
__global__ void headlin_kernel(const float* __restrict__ aggx,
                               const float* __restrict__ W,
                               const float* __restrict__ bias,
                               float* __restrict__ out,
                               float* ssum, float* ssq, int M) {
    constexpr int HC = H * C;
    constexpr int HD = H * DIN;
    extern __shared__ float smem[];
    float* Wsm = smem;
    float* ax  = smem + DIN * HC;
    int tid = threadIdx.x;             // HC threads
    int h = tid / C;

    for (int i = tid; i < DIN * HC; i += HC) Wsm[i] = W[i];

    int n0 = blockIdx.x * NB;
    for (int i = tid; i < NB * HD; i += HC) {
        int r = i / HD, cc = i % HD;
        int n = n0 + r;
        ax[i] = (n < M) ? aggx[(size_t)n * HD + cc] : 0.f;
    }
    __syncthreads();

    float bb = bias[tid];
    float s = 0.f, q2 = 0.f;
    #pragma unroll
    for (int r = 0; r < NB; r++) {
        int n = n0 + r;
        if (n >= M) break;
        float acc = 0.f;
        const float* axr = ax + r * HD + h * DIN;
        #pragma unroll
        for (int k = 0; k < DIN; k++)
            acc += Wsm[k * HC + tid] * axr[k];
        float v = acc + bb;
        out[(size_t)n * HC + tid] = v;
        s += v; q2 += v * v;
    }
    atomicAdd(&ssum[tid], s);
    atomicAdd(&ssq [tid], q2);
}

// ---------------- BN finalize (reads + zeroes accumulators) --------------
__global__ void bn_finalize_kernel(float* ssum, float* ssq,
                                   const float* __restrict__ g, const float* __restrict__ be,
                                   float* scale, float* shift, int M, int D) {
    int f = blockIdx.x * blockDim.x + threadIdx.x;
    if (f >= D) return;
    float inv = 1.f / (float)M;
    float mu = ssum[f] * inv;
    float var = ssq[f] * inv - mu * mu;
    float sc = g[f] * rsqrtf(var + EPS_BN);
    scale[f] = sc;
    shift[f] = be[f] - mu * sc;
    ssum[f] = 0.f;
    ssq [f] = 0.f;
}

// ---------------- pooling: segmented + BN3+ReLU ----------
#define POOL_ROWS 128
__global__ void pool_bn_kernel(const float* __restrict__ h, const int* __restrict__ batch,
                               const float* __restrict__ scale, const float* __restrict__ shift,
                               float* pool, int* cnt, int M) {
    const int D = 384;
    int f = threadIdx.x;
    int r0 = blockIdx.x * POOL_ROWS;
    int rend = min(r0 + POOL_ROWS, M);
    float sc = scale[f], sh = shift[f];
    int cur = __ldg(&batch[r0]);
    float acc = 0.f;
    int count = 0;
    for (int r = r0; r < rend; r++) {
        int b = __ldg(&batch[r]);
        if (b != cur) {
            atomicAdd(&pool[cur * D + f], acc);
            if (f == 0) atomicAdd(&cnt[cur], count);
            acc = 0.f; count = 0; cur = b;
        }
        acc += fmaxf(h[(size_t)r * D + f] * sc + sh, 0.f);
        count++;
    }
    atomicAdd(&pool[cur * D + f], acc);
    if (f == 0) atomicAdd(&cnt[cur], count);
}

__global__ void pool_div_kernel(float* pooled, const float* pool, const int* cnt, int G, int D) {
    int t = blockIdx.x * blockDim.x + threadIdx.x;
    if (t >= G * D) return;
    int g = t / D;
    float c = fmaxf((float)cnt[g], 1.f);
    pooled[t] = pool[t] / c;
}

// ---------------- host-side orchestration ----------------
struct Ptrs {
    float *hx, *agg, *lin, *aggx, *bcat;
    int *deg, *off, *cursor, *csr, *partial;
    float *bnsum, *bnsq, *scale, *shift, *pool, *pooled;
    int *cnt;
};

static void launch_gemm2(const float* A, const float* B, const float* bias,
                         const float* tscale, const float* tshift, float* C,
                         float* ssum, float* ssq, int M, int K, int N) {
    dim3 grid((N + GBN - 1) / GBN, (M + GBM - 1) / GBM);
    gemm_tc_kernel<0><<<grid, 256>>>(A, B, bias, tscale, tshift, C, ssum, ssq, M, K, N);
}
static void launch_gemm3(const float* A, const float* B, const float* bias,
                         const float* tscale, const float* tshift, float* C,
                         float* ssum, float* ssq, int M, int K, int N) {
    dim3 grid((N + GBN - 1) / GBN, (M + GBM - 1) / GBM);
    gemm_tc_kernel<1><<<grid, 256>>>(A, B, bias, tscale, tshift, C, ssum, ssq, M, K, N);
}

extern "C" void kernel_launch(void* const* d_in, const int* in_sizes, int n_in,
                              void* d_out, int out_size) {
    const float* x     = (const float*)d_in[0];
    const int*   ei    = (const int*)  d_in[1];
    const int*   batch = (const int*)  d_in[2];
    const float* W1  = (const float*)d_in[3];
    const float* as1 = (const float*)d_in[4];
    const float* ad1 = (const float*)d_in[5];
    const float* b1  = (const float*)d_in[6];
    const float* g1  = (const float*)d_in[7];
    const float* be1 = (const float*)d_in[8];
    const float* lw1 = (const float*)d_in[9];
    const float* lb1 = (const float*)d_in[10];
    const float* gl1 = (const float*)d_in[11];
    const float* bel1= (const float*)d_in[12];
    const float* W2  = (const float*)d_in[13];
    const float* as2 = (const float*)d_in[14];
    const float* ad2 = (const float*)d_in[15];
    const float* b2  = (const float*)d_in[16];
    const float* g2  = (const float*)d_in[17];
    const float* be2 = (const float*)d_in[18];
    const float* lw2 = (const float*)d_in[19];
    const float* lb2 = (const float*)d_in[20];
    const float* gl2 = (const float*)d_in[21];
    const float* bel2= (const float*)d_in[22];
    const float* W3  = (const float*)d_in[23];
    const float* as3 = (const float*)d_in[24];
    const float* ad3 = (const float*)d_in[25];
    const float* b3  = (const float*)d_in[26];
    const float* g3  = (const float*)d_in[27];
    const float* be3 = (const float*)d_in[28];
    const float* lwf = (const float*)d_in[29];
    const float* lbf = (const float*)d_in[30];

    int M = in_sizes[2];
    int E = in_sizes[1] / 2;
    int EX = E + M;

    Ptrs P;
    cudaGetSymbolAddress((void**)&P.hx, d_hx);
    cudaGetSymbolAddress((void**)&P.agg, d_agg);
    cudaGetSymbolAddress((void**)&P.lin, d_lin);
    cudaGetSymbolAddress((void**)&P.aggx, d_aggx);
    cudaGetSymbolAddress((void**)&P.bcat, d_bcat);
    cudaGetSymbolAddress((void**)&P.deg, d_deg);
    cudaGetSymbolAddress((void**)&P.off, d_off);
    cudaGetSymbolAddress((void**)&P.cursor, d_cursor);
    cudaGetSymbolAddress((void**)&P.csr, d_csr);
    cudaGetSymbolAddress((void**)&P.partial, d_partial);
    cudaGetSymbolAddress((void**)&P.bnsum, d_bnsum);
    cudaGetSymbolAddress((void**)&P.bnsq, d_bnsq);
    cudaGetSymbolAddress((void**)&P.scale, d_scale);
    cudaGetSymbolAddress((void**)&P.shift, d_shift);
    cudaGetSymbolAddress((void**)&P.pool, d_pool);
    cudaGetSymbolAddress((void**)&P.pooled, d_pooled);
    cudaGetSymbolAddress((void**)&P.cnt, d_cnt);

    cudaFuncSetAttribute(headlin_kernel<8, 32, 48, 4>,
                         cudaFuncAttributeMaxDynamicSharedMemorySize, 56 * 1024);
    cudaFuncSetAttribute(headlin_kernel<16, 16, 32, 4>,
                         cudaFuncAttributeMaxDynamicSharedMemorySize, 56 * 1024);

    // ---- init + CSR build ----
    zero_stats_kernel<<<1, 512>>>(P.bnsum, P.bnsq);
    zero_i_kernel<<<(M + 255) / 256, 256>>>(P.deg, M);
    edge_hist_kernel<<<(EX + 255) / 256, 256>>>(ei, E, M, P.deg);
    int nb = (M + 1023) / 1024;
    scan_block_kernel<<<nb, 1024>>>(P.deg, P.off, P.partial, M);
    scan_add_kernel<<<(M + 255) / 256, 256>>>(P.off, P.partial, P.cursor, M, EX);
    edge_scatter_kernel<<<(EX + 255) / 256, 256>>>(ei, E, M, P.cursor, P.csr);

    const int wpb = 8;
    int ablk = (M + wpb - 1) / wpb;

    // ---- Layer 1: GAT(128 -> 20x16=320), NC=360 ----
    build_bcat_kernel<<<(128 * 360 + 255) / 256, 256>>>(W1, as1, ad1, P.bcat, 128, 20, 16);
    launch_gemm2(x, P.bcat, nullptr, nullptr, nullptr, P.hx, nullptr, nullptr, M, 128, 360);
    gat_aggregate_kernel<20, 16><<<ablk, wpb * 32>>>(P.hx, P.off, P.csr, b1, P.agg, P.bnsum, P.bnsq, M);
    bn_finalize_kernel<<<3, 128>>>(P.bnsum, P.bnsq, g1, be1, P.scale, P.shift, M, 320);
    launch_gemm2(P.agg, lw1, lb1, P.scale, P.shift, P.lin, P.bnsum, P.bnsq, M, 320, 16);
    bn_finalize_kernel<<<1, 128>>>(P.bnsum, P.bnsq, gl1, bel1, P.scale, P.shift, M, 16);

    // ---- Layer 2: GAT(16 -> 16x32=512) via input-side aggregation ----
    build_bsc_kernel<<<(16 * 32 + 255) / 256, 256>>>(W2, as2, ad2, P.bcat, 16, 16, 32);
    launch_gemm2(P.lin, P.bcat, nullptr, P.scale, P.shift, P.hx, nullptr, nullptr, M, 16, 32);
    gat_aggx_kernel<16, 16><<<ablk, wpb * 32>>>(P.lin, P.hx, P.scale, P.shift, P.off, P.csr, P.aggx, M);
    {
        int smem = (16 * 512 + 4 * 256) * 4;
        headlin_kernel<16, 16, 32, 4><<<(M + 3) / 4, 512, smem>>>(P.aggx, W2, b2, P.agg, P.bnsum, P.bnsq, M);
    }
    bn_finalize_kernel<<<4, 128>>>(P.bnsum, P.bnsq, g2, be2, P.scale, P.shift, M, 512);
    launch_gemm2(P.agg, lw2, lb2, P.scale, P.shift, P.lin, P.bnsum, P.bnsq, M, 512, 32);
    bn_finalize_kernel<<<1, 128>>>(P.bnsum, P.bnsq, gl2, bel2, P.scale, P.shift, M, 32);

    // ---- Layer 3: GAT(32 -> 8x48=384) via input-side aggregation ----
    build_bsc_kernel<<<(32 * 16 + 255) / 256, 256>>>(W3, as3, ad3, P.bcat, 32, 8, 48);
    launch_gemm2(P.lin, P.bcat, nullptr, P.scale, P.shift, P.hx, nullptr, nullptr, M, 32, 16);
    gat_aggx_kernel<8, 32><<<ablk, wpb * 32>>>(P.lin, P.hx, P.scale, P.shift, P.off, P.csr, P.aggx, M);
    {
        int smem = (32 * 384 + 4 * 256) * 4;
        headlin_kernel<8, 32, 48, 4><<<(M + 3) / 4, 384, smem>>>(P.aggx, W3, b3, P.agg, P.bnsum, P.bnsq, M);
    }
    bn_finalize_kernel<<<3, 128>>>(P.bnsum, P.bnsq, g3, be3, P.scale, P.shift, M, 384);

    // ---- global mean pool (fused BN3+ReLU, segmented) + final linear ----
    zero_pool_kernel<<<(GG * 384 + 255) / 256, 256>>>(P.pool, P.cnt);
    pool_bn_kernel<<<(M + POOL_ROWS - 1) / POOL_ROWS, 384>>>(P.agg, batch, P.scale, P.shift, P.pool, P.cnt, M);
    pool_div_kernel<<<(GG * 384 + 255) / 256, 256>>>(P.pooled, P.pool, P.cnt, GG, 384);
    launch_gemm3(P.pooled, lwf, lbf, nullptr, nullptr, (float*)d_out, nullptr, nullptr, GG, 384, 10);
}